// round 2
// baseline (speedup 1.0000x reference)
#include <cuda_runtime.h>
#include <math.h>

#define Bc 32
#define Sc 32
#define Ec 512
#define Hc 8
#define DHc 64
#define NBc 4
#define Vc 10000
#define KT 16
#define BSE (Bc*Sc*Ec)

// ---------------- device scratch (static, no allocation) ----------------
__device__ float g_Y[BSE];
__device__ float g_XA[BSE];
__device__ float g_XB[BSE];
__device__ float g_qkv[3*BSE];
__device__ float g_attn[BSE];
__device__ float g_h1[BSE];
__device__ float g_h2[BSE];
__device__ float g_u[BSE];
__device__ float g_w[Bc*Sc];
__device__ float g_pe[Sc*Ec];
__device__ float g_Sk[NBc*Ec];
__device__ float g_Sv[NBc*Ec];
__device__ float g_G[NBc*Ec*Hc];
__device__ float g_gbA[NBc*Hc];
__device__ float g_U[NBc*Hc*Ec];
__device__ float g_c0[NBc*Ec];
__device__ float g_logits[Bc*Vc];
__device__ int   g_ids[Bc];

// ---------------- prelude kernels ----------------
__global__ void pe_k() {
    int s = blockIdx.x, tid = threadIdx.x;
    for (int q = 0; q < 2; q++) {
        int e = tid + q*256;
        int j = e >> 1;
        float div = expf((float)(2*j) * (-logf(10000.f) / (float)Ec));
        float a = (float)s * div;
        g_pe[s*Ec + e] = (e & 1) ? cosf(a) : sinf(a);
    }
}

__global__ void w_k(const float* __restrict__ noise, const float* __restrict__ Win,
                    const float* __restrict__ bin) {
    __shared__ float t1[32*32];
    int tid = threadIdx.x;
    int b = tid >> 5, s = tid & 31;
    float a = bin[s];
    for (int k = 0; k < 32; k++) a += noise[b*32 + k] * Win[k*32 + s];
    t1[b*32 + s] = a;
    __syncthreads();
    float a2 = bin[32 + s];
    for (int k = 0; k < 32; k++) a2 += t1[b*32 + k] * Win[1024 + k*32 + s];
    g_w[b*32 + s] = a2;
}

__global__ void colsum_k(const float* __restrict__ Wca) {
    int n = blockIdx.x, which = blockIdx.y;   // 0 -> Sk (Wk), 1 -> Sv (Wv)
    int f = threadIdx.x;
    const float* W = Wca + (size_t)(n*4 + 1 + which) * Ec * Ec;
    float a = 0.f;
    for (int e = 0; e < Ec; e++) a += W[(size_t)e*Ec + f];
    if (which) g_Sv[n*Ec + f] = a; else g_Sk[n*Ec + f] = a;
}

__global__ void gpre_k(const float* __restrict__ Wca, const float* __restrict__ bca) {
    int n = blockIdx.x;
    int e = threadIdx.x;
    const float* Wq = Wca + (size_t)(n*4 + 0) * Ec * Ec;
    const float* Sk = g_Sk + n*Ec;
    for (int h = 0; h < Hc; h++) {
        float a = 0.f;
        for (int d = 0; d < DHc; d++) a += Wq[(size_t)e*Ec + h*DHc + d] * Sk[h*DHc + d];
        g_G[n*Ec*Hc + e*Hc + h] = a;
    }
    if (e < Hc) {
        const float* bq = bca + (n*4 + 0)*Ec;
        float a = 0.f;
        for (int d = 0; d < DHc; d++) a += bq[e*DHc + d] * Sk[e*DHc + d];
        g_gbA[n*Hc + e] = a;
    }
}

__global__ void upre_k(const float* __restrict__ Wca, const float* __restrict__ bca) {
    int n = blockIdx.x;
    int e = threadIdx.x;
    const float* Wo = Wca + (size_t)(n*4 + 3) * Ec * Ec;
    const float* Sv = g_Sv + n*Ec;
    for (int h = 0; h < Hc; h++) {
        float a = 0.f;
        for (int d = 0; d < DHc; d++) a += Sv[h*DHc + d] * Wo[(size_t)(h*DHc + d)*Ec + e];
        g_U[n*Hc*Ec + h*Ec + e] = a;
    }
    const float* bv = bca + (n*4 + 2)*Ec;
    float a = 0.f;
    for (int f = 0; f < Ec; f++) a += bv[f] * Wo[(size_t)f*Ec + e];
    g_c0[n*Ec + e] = a + bca[(n*4 + 3)*Ec + e];
}

__global__ void y0_k(const float* __restrict__ emb) {
    int b = blockIdx.x, tid = threadIdx.x;
    for (int q = 0; q < 2; q++) {
        int e = tid + q*256;
        g_Y[(size_t)b*Sc*Ec + e] = emb[e] + g_pe[e];
    }
}

__global__ void out0_k(float* __restrict__ out) {
    int b = blockIdx.x;
    int col = blockIdx.y*256 + threadIdx.x;
    if (col < Vc) out[(size_t)b*Sc*Vc + col] = (col == 0) ? 1.f : 0.f;
}

// ---------------- GEMM: (t rows per batch) x 512 @ 512x512, fused epilogue ----------------
// mode: 0 = bias, 1 = bias+relu, 2 = bias+residual+LayerNorm
// grid (Bc, ceil(t/8), Z); Z indexes W/bias/out with fixed strides (for fused QKV).
__global__ void __launch_bounds__(256) gemm_k(
    const float* __restrict__ Xin, const float* __restrict__ Wb,
    const float* __restrict__ bb, const float* __restrict__ Res,
    const float* __restrict__ lng, const float* __restrict__ lnb,
    float* __restrict__ Ob, int t, int mode)
{
    int b = blockIdx.x, rs = blockIdx.y, z = blockIdx.z;
    int row0 = rs * 8;
    if (row0 >= t) return;
    int nrows = min(8, t - row0);
    const float* W    = Wb + (size_t)z*Ec*Ec;
    const float* bias = bb + z*Ec;
    float* Out        = Ob + (size_t)z*BSE;

    __shared__ float Ws[KT*Ec];   // 32 KB, reused as C-store for LN
    __shared__ float Xs[8*KT];

    int tid = threadIdx.x;
    int rp = tid >> 6;            // 0..3 (row pair)
    int cg = tid & 63;            // 0..63 (8-col group)
    int c0 = cg << 3;
    const float* Xrow = Xin + ((size_t)b*Sc + row0)*Ec;

    float a0[8], a1[8];
    #pragma unroll
    for (int c = 0; c < 8; c++) { a0[c] = 0.f; a1[c] = 0.f; }

    for (int k0 = 0; k0 < Ec; k0 += KT) {
        const float4* src = (const float4*)(W + (size_t)k0*Ec);
        float4* dst = (float4*)Ws;
        #pragma unroll
        for (int j = 0; j < 8; j++) dst[tid + j*256] = src[tid + j*256];
        if (tid < 128) {
            int r = tid >> 4, c = tid & 15;
            Xs[r*KT + c] = (r < nrows) ? Xrow[(size_t)r*Ec + k0 + c] : 0.f;
        }
        __syncthreads();
        #pragma unroll
        for (int k = 0; k < KT; k++) {
            float x0 = Xs[(rp*2)*KT + k];
            float x1 = Xs[(rp*2+1)*KT + k];
            float wv[8];
            *(float4*)&wv[0] = *(const float4*)&Ws[k*Ec + c0];
            *(float4*)&wv[4] = *(const float4*)&Ws[k*Ec + c0 + 4];
            #pragma unroll
            for (int c = 0; c < 8; c++) {
                a0[c] = fmaf(x0, wv[c], a0[c]);
                a1[c] = fmaf(x1, wv[c], a1[c]);
            }
        }
        __syncthreads();
    }

    int r0 = rp*2, r1 = rp*2 + 1;
    float bv[8];
    #pragma unroll
    for (int c = 0; c < 8; c++) bv[c] = bias[c0 + c];

    if (mode == 2) {
        float* Cs = Ws;  // 8x512
        const float* Rrow = Res + ((size_t)b*Sc + row0)*Ec;
        if (r0 < nrows) {
            #pragma unroll
            for (int c = 0; c < 8; c++) Cs[r0*Ec + c0 + c] = a0[c] + bv[c] + Rrow[(size_t)r0*Ec + c0 + c];
        }
        if (r1 < nrows) {
            #pragma unroll
            for (int c = 0; c < 8; c++) Cs[r1*Ec + c0 + c] = a1[c] + bv[c] + Rrow[(size_t)r1*Ec + c0 + c];
        }
        __syncthreads();
        int w = tid >> 5, lane = tid & 31;
        if (w < nrows) {
            float s = 0.f, s2 = 0.f;
            #pragma unroll
            for (int j = 0; j < 16; j++) {
                float v = Cs[w*Ec + lane + 32*j];
                s += v; s2 += v*v;
            }
            #pragma unroll
            for (int o = 16; o; o >>= 1) {
                s  += __shfl_xor_sync(0xffffffffu, s, o);
                s2 += __shfl_xor_sync(0xffffffffu, s2, o);
            }
            float mu  = s * (1.f/Ec);
            float var = s2 * (1.f/Ec) - mu*mu;
            float inv = rsqrtf(var + 1e-5f);
            float* Orow = Out + ((size_t)b*Sc + row0 + w)*Ec;
            #pragma unroll
            for (int j = 0; j < 16; j++) {
                int c = lane + 32*j;
                float v = Cs[w*Ec + c];
                Orow[c] = lng[c]*(v - mu)*inv + lnb[c];
            }
        }
    } else {
        if (r0 < nrows) {
            float* Orow = Out + ((size_t)b*Sc + row0 + r0)*Ec;
            #pragma unroll
            for (int c = 0; c < 8; c++) {
                float v = a0[c] + bv[c];
                if (mode == 1) v = fmaxf(v, 0.f);
                Orow[c0 + c] = v;
            }
        }
        if (r1 < nrows) {
            float* Orow = Out + ((size_t)b*Sc + row0 + r1)*Ec;
            #pragma unroll
            for (int c = 0; c < 8; c++) {
                float v = a1[c] + bv[c];
                if (mode == 1) v = fmaxf(v, 0.f);
                Orow[c0 + c] = v;
            }
        }
    }
}

// ---------------- self-attention (full, no mask), one block per (b, h) ----------------
__global__ void __launch_bounds__(256) attn_k(int t) {
    int b = blockIdx.x, h = blockIdx.y;
    __shared__ float Qs[32*64];
    __shared__ float Ks[32*65];
    __shared__ float Vs[32*65];
    __shared__ float Ps[32*33];
    int tid = threadIdx.x;
    const float* qb = g_qkv;
    const float* kb = g_qkv + BSE;
    const float* vb = g_qkv + 2*BSE;
    for (int idx = tid; idx < t*64; idx += 256) {
        int i = idx >> 6, d = idx & 63;
        size_t off = ((size_t)b*Sc + i)*Ec + h*DHc + d;
        Qs[i*64 + d] = qb[off];
        Ks[i*65 + d] = kb[off];
        Vs[i*65 + d] = vb[off];
    }
    __syncthreads();
    int lane = tid & 31, wg = tid >> 5;
    // scores
    #pragma unroll
    for (int ii = 0; ii < 4; ii++) {
        int i = wg + 8*ii;
        if (i < t && lane < t) {
            float s = 0.f;
            #pragma unroll
            for (int d = 0; d < 64; d++) s = fmaf(Qs[i*64 + d], Ks[lane*65 + d], s);
            Ps[i*33 + lane] = s * 0.125f;
        }
    }
    __syncthreads();
    // softmax rows
    for (int ii = 0; ii < 4; ii++) {
        int i = wg + 8*ii;
        if (i < t) {
            float v = (lane < t) ? Ps[i*33 + lane] : -3.4e38f;
            float mx = v;
            #pragma unroll
            for (int o = 16; o; o >>= 1) mx = fmaxf(mx, __shfl_xor_sync(0xffffffffu, mx, o));
            float e = (lane < t) ? expf(v - mx) : 0.f;
            float sum = e;
            #pragma unroll
            for (int o = 16; o; o >>= 1) sum += __shfl_xor_sync(0xffffffffu, sum, o);
            if (lane < t) Ps[i*33 + lane] = e / sum;
        }
    }
    __syncthreads();
    // P @ V
    for (int ii = 0; ii < 4; ii++) {
        int i = wg + 8*ii;
        if (i >= t) continue;
        #pragma unroll
        for (int dd = 0; dd < 2; dd++) {
            int d = lane + 32*dd;
            float o = 0.f;
            for (int j = 0; j < t; j++) o = fmaf(Ps[i*33 + j], Vs[j*65 + d], o);
            g_attn[((size_t)b*Sc + i)*Ec + h*DHc + d] = o;
        }
    }
}

// ---------------- collapsed cross-attention + residual + LN, one block per (b, i) ----------------
__global__ void __launch_bounds__(256) ca_k(int n, int t,
        const float* __restrict__ lng_all, const float* __restrict__ lnb_all) {
    int b = blockIdx.x, i = blockIdx.y;
    if (i >= t) return;
    int tid = threadIdx.x;
    __shared__ float hr[512];
    __shared__ float msh[8];
    __shared__ float red[18];
    size_t roff = ((size_t)b*Sc + i)*Ec;
    hr[tid]       = g_h1[roff + tid];
    hr[tid + 256] = g_h1[roff + tid + 256];
    __syncthreads();
    int w = tid >> 5, lane = tid & 31;
    {
        // A[w] = hr . G[:,w] + gbA[w]
        float p = 0.f;
        const float* G = g_G + n*Ec*Hc;
        #pragma unroll
        for (int j = 0; j < 16; j++) {
            int e = lane + 32*j;
            p = fmaf(hr[e], G[e*Hc + w], p);
        }
        #pragma unroll
        for (int o = 16; o; o >>= 1) p += __shfl_xor_sync(0xffffffffu, p, o);
        float A = p + g_gbA[n*Hc + w];
        // m[w] = sum_s softmax_s(w_s * A / 8) * w_s
        float ws = (lane < t) ? g_w[b*Sc + lane] : 0.f;
        float z  = (lane < t) ? ws * A * 0.125f : -3.4e38f;
        float mx = z;
        #pragma unroll
        for (int o = 16; o; o >>= 1) mx = fmaxf(mx, __shfl_xor_sync(0xffffffffu, mx, o));
        float e = (lane < t) ? expf(z - mx) : 0.f;
        float num = e * ws, den = e;
        #pragma unroll
        for (int o = 16; o; o >>= 1) {
            num += __shfl_xor_sync(0xffffffffu, num, o);
            den += __shfl_xor_sync(0xffffffffu, den, o);
        }
        if (lane == 0) msh[w] = num / den;
    }
    __syncthreads();
    const float* U   = g_U  + n*Hc*Ec;
    const float* c0p = g_c0 + n*Ec;
    float vals[2];
    float s = 0.f, s2 = 0.f;
    #pragma unroll
    for (int q = 0; q < 2; q++) {
        int c = tid + q*256;
        float v = hr[c] + c0p[c];
        #pragma unroll
        for (int hh = 0; hh < Hc; hh++) v = fmaf(msh[hh], U[hh*Ec + c], v);
        vals[q] = v; s += v; s2 += v*v;
    }
    #pragma unroll
    for (int o = 16; o; o >>= 1) {
        s  += __shfl_xor_sync(0xffffffffu, s, o);
        s2 += __shfl_xor_sync(0xffffffffu, s2, o);
    }
    if (lane == 0) { red[w] = s; red[8 + w] = s2; }
    __syncthreads();
    if (tid == 0) {
        float S = 0.f, S2 = 0.f;
        for (int k = 0; k < 8; k++) { S += red[k]; S2 += red[8 + k]; }
        red[16] = S; red[17] = S2;
    }
    __syncthreads();
    float mu  = red[16] * (1.f/Ec);
    float inv = rsqrtf(red[17]*(1.f/Ec) - mu*mu + 1e-5f);
    const float* lg = lng_all + (n*3 + 1)*Ec;
    const float* lb = lnb_all + (n*3 + 1)*Ec;
    #pragma unroll
    for (int q = 0; q < 2; q++) {
        int c = tid + q*256;
        g_h2[roff + c] = lg[c]*(vals[q] - mu)*inv + lb[c];
    }
}

// ---------------- logits: row (b, t-1) @ soft_W + soft_b ----------------
__global__ void __launch_bounds__(256) logits_k(const float* __restrict__ sw,
        const float* __restrict__ sb, int t) {
    int b = blockIdx.x;
    __shared__ float xr[512];
    int tid = threadIdx.x;
    size_t roff = ((size_t)b*Sc + (t - 1))*Ec;
    xr[tid]       = g_XB[roff + tid];
    xr[tid + 256] = g_XB[roff + tid + 256];
    __syncthreads();
    int col = blockIdx.y*256 + tid;
    if (col < Vc) {
        float a = sb[col];
        #pragma unroll 8
        for (int k = 0; k < Ec; k++) a = fmaf(xr[k], sw[(size_t)k*Vc + col], a);
        g_logits[(size_t)b*Vc + col] = a;
    }
}

// ---------------- softmax + argmax (first-max tie break), write probs ----------------
__global__ void __launch_bounds__(256) smax_k(float* __restrict__ out, int t) {
    int b = blockIdx.x, tid = threadIdx.x;
    __shared__ float sv[256];
    __shared__ int   si[256];
    __shared__ float ss[256];
    const float* L = g_logits + (size_t)b*Vc;
    float bestv = -3.4e38f; int besti = 0;
    for (int c = tid; c < Vc; c += 256) {
        float v = L[c];
        if (v > bestv) { bestv = v; besti = c; }
    }
    sv[tid] = bestv; si[tid] = besti;
    __syncthreads();
    for (int o = 128; o; o >>= 1) {
        if (tid < o) {
            float ov = sv[tid + o]; int oi = si[tid + o];
            if (ov > sv[tid] || (ov == sv[tid] && oi < si[tid])) { sv[tid] = ov; si[tid] = oi; }
        }
        __syncthreads();
    }
    float mx = sv[0];
    float s = 0.f;
    for (int c = tid; c < Vc; c += 256) s += expf(L[c] - mx);
    ss[tid] = s;
    __syncthreads();
    for (int o = 128; o; o >>= 1) {
        if (tid < o) ss[tid] += ss[tid + o];
        __syncthreads();
    }
    float inv = 1.f / ss[0];
    float* orow = out + ((size_t)b*Sc + t)*Vc;
    for (int c = tid; c < Vc; c += 256) orow[c] = expf(L[c] - mx) * inv;
    if (tid == 0) g_ids[b] = si[0];
}

__global__ void embed_k(const float* __restrict__ emb, int t) {
    int b = blockIdx.x, tid = threadIdx.x;
    int id = g_ids[b];
    size_t yoff = ((size_t)b*Sc + t)*Ec;
    for (int q = 0; q < 2; q++) {
        int e = tid + q*256;
        g_Y[yoff + e] = emb[(size_t)id*Ec + e] + g_pe[t*Ec + e];
    }
}

// ---------------- host ----------------
extern "C" void kernel_launch(void* const* d_in, const int* in_sizes, int n_in,
                              void* d_out, int out_size) {
    const float* noise = (const float*)d_in[0];
    const float* W_in  = (const float*)d_in[1];
    const float* b_in  = (const float*)d_in[2];
    const float* emb   = (const float*)d_in[3];
    const float* Wsa   = (const float*)d_in[4];
    const float* bsa   = (const float*)d_in[5];
    const float* Wca   = (const float*)d_in[6];
    const float* bca   = (const float*)d_in[7];
    const float* Wff   = (const float*)d_in[8];
    const float* bff   = (const float*)d_in[9];
    const float* lng   = (const float*)d_in[10];
    const float* lnb   = (const float*)d_in[11];
    const float* sw    = (const float*)d_in[12];
    const float* sb    = (const float*)d_in[13];
    float* out = (float*)d_out;

    float *pY, *pXA, *pXB, *pqkv, *pattn, *ph1, *ph2, *pu;
    cudaGetSymbolAddress((void**)&pY,   g_Y);
    cudaGetSymbolAddress((void**)&pXA,  g_XA);
    cudaGetSymbolAddress((void**)&pXB,  g_XB);
    cudaGetSymbolAddress((void**)&pqkv, g_qkv);
    cudaGetSymbolAddress((void**)&pattn,g_attn);
    cudaGetSymbolAddress((void**)&ph1,  g_h1);
    cudaGetSymbolAddress((void**)&ph2,  g_h2);
    cudaGetSymbolAddress((void**)&pu,   g_u);

    pe_k<<<Sc, 256>>>();
    w_k<<<1, 1024>>>(noise, W_in, b_in);
    colsum_k<<<dim3(NBc, 2), 512>>>(Wca);
    gpre_k<<<NBc, 512>>>(Wca, bca);
    upre_k<<<NBc, 512>>>(Wca, bca);
    y0_k<<<Bc, 256>>>(emb);
    out0_k<<<dim3(Bc, 40), 256>>>(out);

    for (int t = 1; t < Sc; t++) {
        int nrs = (t + 7) / 8;   // dynamic row-split count (known at capture time)
        const float* in = pY;
        float* outs[4] = {pXA, pXB, pXA, pXB};
        for (int n = 0; n < NBc; n++) {
            // fused QKV projection (z = 0,1,2)
            gemm_k<<<dim3(Bc, nrs, 3), 256>>>(in, Wsa + (size_t)n*4*Ec*Ec, bsa + n*4*Ec,
                                              nullptr, nullptr, nullptr, pqkv, t, 0);
            attn_k<<<dim3(Bc, Hc), 256>>>(t);
            // O-proj + bias + residual(in) + LN
            gemm_k<<<dim3(Bc, nrs, 1), 256>>>(pattn, Wsa + ((size_t)n*4 + 3)*Ec*Ec,
                                              bsa + (n*4 + 3)*Ec, in,
                                              lng + (n*3 + 0)*Ec, lnb + (n*3 + 0)*Ec,
                                              ph1, t, 2);
            // collapsed cross-attn + residual + LN
            ca_k<<<dim3(Bc, t), 256>>>(n, t, lng, lnb);
            // FF1 + relu
            gemm_k<<<dim3(Bc, nrs, 1), 256>>>(ph2, Wff + (size_t)(n*2)*Ec*Ec, bff + n*2*Ec,
                                              nullptr, nullptr, nullptr, pu, t, 1);
            // FF2 + bias + residual(h2) + LN
            gemm_k<<<dim3(Bc, nrs, 1), 256>>>(pu, Wff + (size_t)(n*2 + 1)*Ec*Ec,
                                              bff + (n*2 + 1)*Ec, ph2,
                                              lng + (n*3 + 2)*Ec, lnb + (n*3 + 2)*Ec,
                                              outs[n], t, 2);
            in = outs[n];
        }
        logits_k<<<dim3(Bc, 40), 256>>>(sw, sb, t);
        smax_k<<<Bc, 256>>>(out, t);
        embed_k<<<Bc, 256>>>(emb, t);
    }
}

// round 5
// speedup vs baseline: 1.3047x; 1.3047x over previous
#include <cuda_runtime.h>
#include <math.h>

#define Bc 32
#define Sc 32
#define Ec 512
#define Hc 8
#define DHc 64
#define NBc 4
#define Vc 10000
#define BSE (Bc*Sc*Ec)

#define BMt 64
#define BNt 64
#define BKt 16
#define ASTR (BMt + 4)   // 68 floats: 16B-aligned rows (68*4=272), 2-way write conflict only

// ---------------- device scratch ----------------
__device__ float g_Y[BSE];
__device__ float g_XA[BSE];
__device__ float g_XB[BSE];
__device__ float g_qkv[3*BSE];
__device__ float g_attn[BSE];
__device__ float g_C[BSE];       // gemm scratch
__device__ float g_h2[BSE];
__device__ float g_u[BSE];
__device__ float g_w[Bc*Sc];
__device__ float g_pe[Sc*Ec];
__device__ float g_Sk[NBc*Ec];
__device__ float g_Sv[NBc*Ec];
__device__ float g_G[NBc*Ec*Hc];
__device__ float g_gbA[NBc*Hc];
__device__ float g_U[NBc*Hc*Ec];
__device__ float g_c0[NBc*Ec];
__device__ float g_logits[Bc*Vc];
__device__ float g_cpart[8*8*Ec];    // colsum partials (n*2+w, chunk, f)
__device__ float g_c0part[NBc*8*Ec];

// ---------------- prelude ----------------
__global__ void pe_k() {
    int s = blockIdx.x, tid = threadIdx.x;
    for (int q = 0; q < 2; q++) {
        int e = tid + q*256;
        int j = e >> 1;
        float div = expf((float)(2*j) * (-logf(10000.f) / (float)Ec));
        float a = (float)s * div;
        g_pe[s*Ec + e] = (e & 1) ? cosf(a) : sinf(a);
    }
}

__global__ void w_k(const float* __restrict__ noise, const float* __restrict__ Win,
                    const float* __restrict__ bin) {
    __shared__ float t1[32*32];
    int tid = threadIdx.x;
    int b = tid >> 5, s = tid & 31;
    float a = bin[s];
    for (int k = 0; k < 32; k++) a += noise[b*32 + k] * Win[k*32 + s];
    t1[b*32 + s] = a;
    __syncthreads();
    float a2 = bin[32 + s];
    for (int k = 0; k < 32; k++) a2 += t1[b*32 + k] * Win[1024 + k*32 + s];
    g_w[b*32 + s] = a2;
}

// colsum of Wk/Wv, stage 1: e-chunks of 64
__global__ void colsum1_k(const float* __restrict__ Wca) {
    int n = blockIdx.x, which = blockIdx.y, chunk = blockIdx.z;
    int f = threadIdx.x;
    const float* W = Wca + (size_t)(n*4 + 1 + which) * Ec * Ec + (size_t)chunk*64*Ec;
    float a = 0.f;
    for (int e = 0; e < 64; e++) a += W[(size_t)e*Ec + f];
    g_cpart[((n*2 + which)*8 + chunk)*Ec + f] = a;
}
__global__ void colsum2_k() {
    int n = blockIdx.x, which = blockIdx.y;
    int f = threadIdx.x;
    float a = 0.f;
    for (int c = 0; c < 8; c++) a += g_cpart[((n*2 + which)*8 + c)*Ec + f];
    if (which) g_Sv[n*Ec + f] = a; else g_Sk[n*Ec + f] = a;
}

// G[n][e][h] = sum_d Wq[e][h*64+d]*Sk[h*64+d]; gbA[n][h] = sum_d bq[h*64+d]*Sk[h*64+d]
__global__ void gpre_k(const float* __restrict__ Wca, const float* __restrict__ bca) {
    int n = blockIdx.x, h = blockIdx.y;
    __shared__ float sk[64];
    int tid = threadIdx.x;
    if (tid < 64) sk[tid] = g_Sk[n*Ec + h*64 + tid];
    __syncthreads();
    const float* Wq = Wca + (size_t)(n*4) * Ec * Ec;
    for (int e = tid; e < Ec; e += 256) {
        const float* row = Wq + (size_t)e*Ec + h*64;
        float a = 0.f;
        #pragma unroll
        for (int d = 0; d < 64; d += 4) {
            float4 w4 = *(const float4*)&row[d];
            a += w4.x*sk[d] + w4.y*sk[d+1] + w4.z*sk[d+2] + w4.w*sk[d+3];
        }
        g_G[n*Ec*Hc + e*Hc + h] = a;
    }
    if (tid == 0) {
        const float* bq = bca + (n*4)*Ec + h*64;
        float a = 0.f;
        for (int d = 0; d < 64; d++) a += bq[d]*sk[d];
        g_gbA[n*Hc + h] = a;
    }
}

// U[n][h][e] = sum_d Sv[h*64+d]*Wo[h*64+d][e]
__global__ void upre_k(const float* __restrict__ Wca) {
    int n = blockIdx.x, h = blockIdx.y;
    __shared__ float sv[64];
    int tid = threadIdx.x;
    if (tid < 64) sv[tid] = g_Sv[n*Ec + h*64 + tid];
    __syncthreads();
    const float* Wo = Wca + (size_t)(n*4 + 3) * Ec * Ec;
    for (int e = tid; e < Ec; e += 512) {
        float a = 0.f;
        for (int d = 0; d < 64; d++) a += sv[d] * Wo[(size_t)(h*64 + d)*Ec + e];
        g_U[n*Hc*Ec + h*Ec + e] = a;
    }
}

// c0 partials: sum over f-chunk of bv[f]*Wo[f][e]
__global__ void c0a_k(const float* __restrict__ Wca, const float* __restrict__ bca) {
    int n = blockIdx.x, chunk = blockIdx.y;
    int e = threadIdx.x;
    const float* Wo = Wca + (size_t)(n*4 + 3) * Ec * Ec;
    const float* bv = bca + (n*4 + 2)*Ec;
    float a = 0.f;
    for (int f = chunk*64; f < chunk*64 + 64; f++) a += bv[f] * Wo[(size_t)f*Ec + e];
    g_c0part[(n*8 + chunk)*Ec + e] = a;
}
__global__ void c0b_k(const float* __restrict__ bca) {
    int n = blockIdx.x;
    int e = threadIdx.x;
    float a = bca[(n*4 + 3)*Ec + e];
    for (int c = 0; c < 8; c++) a += g_c0part[(n*8 + c)*Ec + e];
    g_c0[n*Ec + e] = a;
}

__global__ void y0_k(const float* __restrict__ emb) {
    int b = blockIdx.x, tid = threadIdx.x;
    for (int q = 0; q < 2; q++) {
        int e = tid + q*256;
        g_Y[(size_t)b*Sc*Ec + e] = emb[e] + g_pe[e];
    }
}

__global__ void out0_k(float* __restrict__ out) {
    int b = blockIdx.x;
    int col = blockIdx.y*256 + threadIdx.x;
    if (col < Vc) out[(size_t)b*Sc*Vc + col] = (col == 0) ? 1.f : 0.f;
}

// ---------------- batched tiled GEMM ----------------
// C[M x 512] = A[M x 512] @ W[512 x 512] + bias, optional relu.
// Rows r -> (b = r/t, i = r%t), stored at (b*Sc+i)*Ec.
// grid (ceil(M/64), 8, Z) — Z strides W by Ec*Ec, bias by Ec, Out by BSE.
__global__ void __launch_bounds__(256) gemm_k(
    const float* __restrict__ A, const float* __restrict__ Wb,
    const float* __restrict__ bb, float* __restrict__ Ob,
    int t, int M, int relu)
{
    int rt = blockIdx.x, ct = blockIdx.y, z = blockIdx.z;
    const float* W    = Wb + (size_t)z*Ec*Ec;
    const float* bias = bb + (size_t)z*Ec;
    float* Out        = Ob + (size_t)z*BSE;

    __shared__ float As[BKt][ASTR];   // 68-float stride: float4-aligned rows
    __shared__ float Bs[BKt][BNt];
    __shared__ int rowOff[BMt];

    int tid = threadIdx.x;
    int row0 = rt * BMt;
    if (tid < BMt) {
        int g = row0 + tid;
        int gg = (g < M) ? g : 0;
        int b = gg / t, i = gg - b*t;
        rowOff[tid] = (b*Sc + i)*Ec;
    }
    __syncthreads();

    int lk = tid & 15, lr = tid >> 4;         // A loader
    int kb = tid >> 4, cb = (tid & 15) * 4;   // B loader
    int tx = tid & 15, ty = tid >> 4;         // compute map
    int c0 = ct * BNt;

    float acc[4][4];
    #pragma unroll
    for (int r = 0; r < 4; r++)
        #pragma unroll
        for (int c = 0; c < 4; c++) acc[r][c] = 0.f;

    for (int k0 = 0; k0 < Ec; k0 += BKt) {
        #pragma unroll
        for (int p = 0; p < 4; p++) {
            int r = lr + p*16;
            int g = row0 + r;
            float v = 0.f;
            if (g < M) v = A[(size_t)rowOff[r] + k0 + lk];
            As[lk][r] = v;
        }
        *(float4*)&Bs[kb][cb] = *(const float4*)&W[(size_t)(k0 + kb)*Ec + c0 + cb];
        __syncthreads();
        #pragma unroll
        for (int k = 0; k < BKt; k++) {
            float a4[4], b4[4];
            *(float4*)a4 = *(const float4*)&As[k][ty*4];
            *(float4*)b4 = *(const float4*)&Bs[k][tx*4];
            #pragma unroll
            for (int r = 0; r < 4; r++)
                #pragma unroll
                for (int c = 0; c < 4; c++)
                    acc[r][c] = fmaf(a4[r], b4[c], acc[r][c]);
        }
        __syncthreads();
    }

    float bv[4];
    *(float4*)bv = *(const float4*)&bias[c0 + tx*4];
    #pragma unroll
    for (int r = 0; r < 4; r++) {
        int lrow = ty*4 + r;
        int g = row0 + lrow;
        if (g < M) {
            float4 o;
            o.x = acc[r][0] + bv[0];
            o.y = acc[r][1] + bv[1];
            o.z = acc[r][2] + bv[2];
            o.w = acc[r][3] + bv[3];
            if (relu) {
                o.x = fmaxf(o.x, 0.f); o.y = fmaxf(o.y, 0.f);
                o.z = fmaxf(o.z, 0.f); o.w = fmaxf(o.w, 0.f);
            }
            *(float4*)&Out[(size_t)rowOff[lrow] + c0 + tx*4] = o;
        }
    }
}

// ---------------- residual + LayerNorm (warp per row) ----------------
__global__ void __launch_bounds__(256) ln_k(
    const float* __restrict__ C, const float* __restrict__ Res,
    const float* __restrict__ lg, const float* __restrict__ lb,
    float* __restrict__ Out, int t, int M)
{
    int gr = blockIdx.x*8 + (threadIdx.x >> 5);
    if (gr >= M) return;
    int lane = threadIdx.x & 31;
    int b = gr / t, i = gr - b*t;
    size_t roff = (size_t)(b*Sc + i)*Ec;
    float v[16];
    float s = 0.f, s2 = 0.f;
    #pragma unroll
    for (int j = 0; j < 16; j++) {
        float x = C[roff + lane + 32*j] + Res[roff + lane + 32*j];
        v[j] = x; s += x; s2 += x*x;
    }
    #pragma unroll
    for (int o = 16; o; o >>= 1) {
        s  += __shfl_xor_sync(0xffffffffu, s, o);
        s2 += __shfl_xor_sync(0xffffffffu, s2, o);
    }
    float mu  = s * (1.f/Ec);
    float inv = rsqrtf(s2*(1.f/Ec) - mu*mu + 1e-5f);
    #pragma unroll
    for (int j = 0; j < 16; j++) {
        int c = lane + 32*j;
        Out[roff + c] = lg[c]*(v[j] - mu)*inv + lb[c];
    }
}

// ---------------- self-attention ----------------
__global__ void __launch_bounds__(256) attn_k(int t) {
    int b = blockIdx.x, h = blockIdx.y;
    __shared__ float Qs[32*64];
    __shared__ float Ks[32*65];
    __shared__ float Vs[32*65];
    __shared__ float Ps[32*33];
    int tid = threadIdx.x;
    const float* qb = g_qkv;
    const float* kb = g_qkv + BSE;
    const float* vb = g_qkv + 2*BSE;
    for (int idx = tid; idx < t*64; idx += 256) {
        int i = idx >> 6, d = idx & 63;
        size_t off = ((size_t)b*Sc + i)*Ec + h*DHc + d;
        Qs[i*64 + d] = qb[off];
        Ks[i*65 + d] = kb[off];
        Vs[i*65 + d] = vb[off];
    }
    __syncthreads();
    int lane = tid & 31, wg = tid >> 5;
    #pragma unroll
    for (int ii = 0; ii < 4; ii++) {
        int i = wg + 8*ii;
        if (i < t && lane < t) {
            float s = 0.f;
            #pragma unroll
            for (int d = 0; d < 64; d++) s = fmaf(Qs[i*64 + d], Ks[lane*65 + d], s);
            Ps[i*33 + lane] = s * 0.125f;
        }
    }
    __syncthreads();
    for (int ii = 0; ii < 4; ii++) {
        int i = wg + 8*ii;
        if (i < t) {
            float v = (lane < t) ? Ps[i*33 + lane] : -3.4e38f;
            float mx = v;
            #pragma unroll
            for (int o = 16; o; o >>= 1) mx = fmaxf(mx, __shfl_xor_sync(0xffffffffu, mx, o));
            float e = (lane < t) ? expf(v - mx) : 0.f;
            float sum = e;
            #pragma unroll
            for (int o = 16; o; o >>= 1) sum += __shfl_xor_sync(0xffffffffu, sum, o);
            if (lane < t) Ps[i*33 + lane] = e / sum;
        }
    }
    __syncthreads();
    for (int ii = 0; ii < 4; ii++) {
        int i = wg + 8*ii;
        if (i >= t) continue;
        #pragma unroll
        for (int dd = 0; dd < 2; dd++) {
            int d = lane + 32*dd;
            float o = 0.f;
            for (int j = 0; j < t; j++) o = fmaf(Ps[i*33 + j], Vs[j*65 + d], o);
            g_attn[((size_t)b*Sc + i)*Ec + h*DHc + d] = o;
        }
    }
}

// ---------------- fused: LN0(C+Res) -> collapsed cross-attn -> LN1 -> g_h2 ----------------
__global__ void __launch_bounds__(256) ca_k(int n, int t,
        const float* __restrict__ C, const float* __restrict__ Res,
        const float* __restrict__ lng_all, const float* __restrict__ lnb_all) {
    int b = blockIdx.x, i = blockIdx.y;
    int tid = threadIdx.x;
    __shared__ float hr[512];
    __shared__ float msh[8];
    __shared__ float red[16];
    __shared__ float redf[2];
    size_t roff = ((size_t)b*Sc + i)*Ec;
    int w = tid >> 5, lane = tid & 31;

    // entry LN (index n*3+0)
    float v0 = C[roff + tid]       + Res[roff + tid];
    float v1 = C[roff + tid + 256] + Res[roff + tid + 256];
    {
        float s = v0 + v1, s2 = v0*v0 + v1*v1;
        #pragma unroll
        for (int o = 16; o; o >>= 1) {
            s  += __shfl_xor_sync(0xffffffffu, s, o);
            s2 += __shfl_xor_sync(0xffffffffu, s2, o);
        }
        if (lane == 0) { red[w] = s; red[8 + w] = s2; }
        __syncthreads();
        if (tid == 0) {
            float S = 0.f, S2 = 0.f;
            for (int k = 0; k < 8; k++) { S += red[k]; S2 += red[8 + k]; }
            redf[0] = S; redf[1] = S2;
        }
        __syncthreads();
        float mu  = redf[0] * (1.f/Ec);
        float inv = rsqrtf(redf[1]*(1.f/Ec) - mu*mu + 1e-5f);
        const float* g0 = lng_all + (n*3 + 0)*Ec;
        const float* b0 = lnb_all + (n*3 + 0)*Ec;
        hr[tid]       = g0[tid]      *(v0 - mu)*inv + b0[tid];
        hr[tid + 256] = g0[tid + 256]*(v1 - mu)*inv + b0[tid + 256];
    }
    __syncthreads();

    // collapsed cross-attention
    {
        float p = 0.f;
        const float* G = g_G + n*Ec*Hc;
        #pragma unroll
        for (int j = 0; j < 16; j++) {
            int e = lane + 32*j;
            p = fmaf(hr[e], G[e*Hc + w], p);
        }
        #pragma unroll
        for (int o = 16; o; o >>= 1) p += __shfl_xor_sync(0xffffffffu, p, o);
        float A = p + g_gbA[n*Hc + w];
        float ws = (lane < t) ? g_w[b*Sc + lane] : 0.f;
        float z  = (lane < t) ? ws * A * 0.125f : -3.4e38f;
        float mx = z;
        #pragma unroll
        for (int o = 16; o; o >>= 1) mx = fmaxf(mx, __shfl_xor_sync(0xffffffffu, mx, o));
        float e = (lane < t) ? expf(z - mx) : 0.f;
        float num = e * ws, den = e;
        #pragma unroll
        for (int o = 16; o; o >>= 1) {
            num += __shfl_xor_sync(0xffffffffu, num, o);
            den += __shfl_xor_sync(0xffffffffu, den, o);
        }
        if (lane == 0) msh[w] = num / den;
    }
    __syncthreads();

    // out = hr + m@U + c0, then LN1 (index n*3+1)
    const float* U   = g_U  + n*Hc*Ec;
    const float* c0p = g_c0 + n*Ec;
    float vals[2];
    float s = 0.f, s2 = 0.f;
    #pragma unroll
    for (int q = 0; q < 2; q++) {
        int c = tid + q*256;
        float v = hr[c] + c0p[c];
        #pragma unroll
        for (int hh = 0; hh < Hc; hh++) v = fmaf(msh[hh], U[hh*Ec + c], v);
        vals[q] = v; s += v; s2 += v*v;
    }
    #pragma unroll
    for (int o = 16; o; o >>= 1) {
        s  += __shfl_xor_sync(0xffffffffu, s, o);
        s2 += __shfl_xor_sync(0xffffffffu, s2, o);
    }
    __syncthreads();
    if (lane == 0) { red[w] = s; red[8 + w] = s2; }
    __syncthreads();
    if (tid == 0) {
        float S = 0.f, S2 = 0.f;
        for (int k = 0; k < 8; k++) { S += red[k]; S2 += red[8 + k]; }
        redf[0] = S; redf[1] = S2;
    }
    __syncthreads();
    float mu  = redf[0] * (1.f/Ec);
    float inv = rsqrtf(redf[1]*(1.f/Ec) - mu*mu + 1e-5f);
    const float* lg = lng_all + (n*3 + 1)*Ec;
    const float* lb = lnb_all + (n*3 + 1)*Ec;
    #pragma unroll
    for (int q = 0; q < 2; q++) {
        int c = tid + q*256;
        g_h2[roff + c] = lg[c]*(vals[q] - mu)*inv + lb[c];
    }
}

// ---------------- logits: rows (b, t-1) @ soft_W + soft_b ----------------
// grid (157, 2): 64 cols x 16 batches per block
__global__ void __launch_bounds__(256) logits_k(const float* __restrict__ sw,
        const float* __restrict__ sb, int t) {
    __shared__ float Xs[16][512];
    int bg = blockIdx.y;
    int tid = threadIdx.x;
    for (int idx = tid; idx < 16*512; idx += 256) {
        int r = idx >> 9, k = idx & 511;
        Xs[r][k] = g_XB[((size_t)(16*bg + r)*Sc + (t - 1))*Ec + k];
    }
    __syncthreads();
    int c = blockIdx.x*64 + (tid & 63);
    int b0 = (tid >> 6) * 4;
    if (c < Vc) {
        float acc[4] = {0.f, 0.f, 0.f, 0.f};
        #pragma unroll 8
        for (int k = 0; k < 512; k++) {
            float wv = sw[(size_t)k*Vc + c];
            #pragma unroll
            for (int j = 0; j < 4; j++) acc[j] = fmaf(Xs[b0 + j][k], wv, acc[j]);
        }
        float bias = sb[c];
        #pragma unroll
        for (int j = 0; j < 4; j++)
            g_logits[(size_t)(16*bg + b0 + j)*Vc + c] = acc[j] + bias;
    }
}

// ---------------- softmax + argmax + fused embed ----------------
__global__ void __launch_bounds__(256) smax_k(float* __restrict__ out,
        const float* __restrict__ emb, int t) {
    int b = blockIdx.x, tid = threadIdx.x;
    __shared__ float sv[256];
    __shared__ int   si[256];
    __shared__ float ss[256];
    const float* L = g_logits + (size_t)b*Vc;
    float bestv = -3.4e38f; int besti = 0;
    for (int c = tid; c < Vc; c += 256) {
        float v = L[c];
        if (v > bestv) { bestv = v; besti = c; }
    }
    sv[tid] = bestv; si[tid] = besti;
    __syncthreads();
    for (int o = 128; o; o >>= 1) {
        if (tid < o) {
            float ov = sv[tid + o]; int oi = si[tid + o];
            if (ov > sv[tid] || (ov == sv[tid] && oi < si[tid])) { sv[tid] = ov; si[tid] = oi; }
        }
        __syncthreads();
    }
    float mx = sv[0];
    float s = 0.f;
    for (int c = tid; c < Vc; c += 256) s += expf(L[c] - mx);
    ss[tid] = s;
    __syncthreads();
    for (int o = 128; o; o >>= 1) {
        if (tid < o) ss[tid] += ss[tid + o];
        __syncthreads();
    }
    float inv = 1.f / ss[0];
    float* orow = out + ((size_t)b*Sc + t)*Vc;
    for (int c = tid; c < Vc; c += 256) orow[c] = expf(L[c] - mx) * inv;
    // fused embed of argmax token
    int id = si[0];
    size_t yoff = ((size_t)b*Sc + t)*Ec;
    for (int e = tid; e < Ec; e += 256)
        g_Y[yoff + e] = emb[(size_t)id*Ec + e] + g_pe[t*Ec + e];
}

// ---------------- host ----------------
extern "C" void kernel_launch(void* const* d_in, const int* in_sizes, int n_in,
                              void* d_out, int out_size) {
    const float* noise = (const float*)d_in[0];
    const float* W_in  = (const float*)d_in[1];
    const float* b_in  = (const float*)d_in[2];
    const float* emb   = (const float*)d_in[3];
    const float* Wsa   = (const float*)d_in[4];
    const float* bsa   = (const float*)d_in[5];
    const float* Wca   = (const float*)d_in[6];
    const float* bca   = (const float*)d_in[7];
    const float* Wff   = (const float*)d_in[8];
    const float* bff   = (const float*)d_in[9];
    const float* lng   = (const float*)d_in[10];
    const float* lnb   = (const float*)d_in[11];
    const float* sw    = (const float*)d_in[12];
    const float* sb    = (const float*)d_in[13];
    float* out = (float*)d_out;

    float *pY, *pXA, *pXB, *pqkv, *pattn, *pC, *ph2, *pu;
    cudaGetSymbolAddress((void**)&pY,   g_Y);
    cudaGetSymbolAddress((void**)&pXA,  g_XA);
    cudaGetSymbolAddress((void**)&pXB,  g_XB);
    cudaGetSymbolAddress((void**)&pqkv, g_qkv);
    cudaGetSymbolAddress((void**)&pattn,g_attn);
    cudaGetSymbolAddress((void**)&pC,   g_C);
    cudaGetSymbolAddress((void**)&ph2,  g_h2);
    cudaGetSymbolAddress((void**)&pu,   g_u);

    pe_k<<<Sc, 256>>>();
    w_k<<<1, 1024>>>(noise, W_in, b_in);
    colsum1_k<<<dim3(NBc, 2, 8), 512>>>(Wca);
    colsum2_k<<<dim3(NBc, 2), 512>>>();
    gpre_k<<<dim3(NBc, Hc), 256>>>(Wca, bca);
    upre_k<<<dim3(NBc, Hc), 512>>>(Wca);
    c0a_k<<<dim3(NBc, 8), 512>>>(Wca, bca);
    c0b_k<<<NBc, 512>>>(bca);
    y0_k<<<Bc, 256>>>(emb);
    out0_k<<<dim3(Bc, 40), 256>>>(out);

    for (int t = 1; t < Sc; t++) {
        int M = Bc * t;
        int rt = (M + BMt - 1) / BMt;
        const float* in = pY;
        float* outs[4] = {pXA, pXB, pXA, pXB};
        for (int n = 0; n < NBc; n++) {
            // fused QKV projection
            gemm_k<<<dim3(rt, 8, 3), 256>>>(in, Wsa + (size_t)n*4*Ec*Ec,
                                            bsa + (size_t)n*4*Ec, pqkv, t, M, 0);
            attn_k<<<dim3(Bc, Hc), 256>>>(t);
            // O-projection (bias only; LN fused into ca_k)
            gemm_k<<<dim3(rt, 8, 1), 256>>>(pattn, Wsa + ((size_t)n*4 + 3)*Ec*Ec,
                                            bsa + (size_t)(n*4 + 3)*Ec, pC, t, M, 0);
            // LN0(C+in) -> collapsed cross-attn -> LN1 -> h2
            ca_k<<<dim3(Bc, t), 256>>>(n, t, pC, in, lng, lnb);
            // FF1 + relu
            gemm_k<<<dim3(rt, 8, 1), 256>>>(ph2, Wff + (size_t)(n*2)*Ec*Ec,
                                            bff + (size_t)(n*2)*Ec, pu, t, M, 1);
            // FF2
            gemm_k<<<dim3(rt, 8, 1), 256>>>(pu, Wff + (size_t)(n*2 + 1)*Ec*Ec,
                                            bff + (size_t)(n*2 + 1)*Ec, pC, t, M, 0);
            // LN2(C + h2)
            ln_k<<<(M + 7)/8, 256>>>(pC, ph2, lng + (size_t)(n*3 + 2)*Ec,
                                     lnb + (size_t)(n*3 + 2)*Ec, outs[n], t, M);
            in = outs[n];
        }
        logits_k<<<dim3((Vc + 63)/64, 2), 256>>>(sw, sb, t);
        smax_k<<<Bc, 256>>>(out, emb, t);
    }
}